// round 1
// baseline (speedup 1.0000x reference)
#include <cuda_runtime.h>
#include <math.h>

// ---------------- problem constants ----------------
#define Bsz   4
#define C_IN  3
#define Hh    60
#define Ww    60
#define NPIX  3600          // H*W
#define HID   64
#define FEAT  128
#define NBT   16            // 4 warps x 4 batches
#define MTX   12960000ULL   // NPIX*NPIX

// ---------------- device scratch (static: no allocation in kernel_launch) ----
__device__ float g_thetaA[NBT][6];
__device__ float g_thetaB[NBT][6];
__device__ float g_xw  [NBT * C_IN * NPIX];            // sampled input, planar
__device__ float g_h   [(size_t)NBT * NPIX * HID];     // conv1 out [bt][p][64]
__device__ float g_y   [(size_t)NBT * NPIX * FEAT];    // conv2 out [bt][p][128]
__device__ float g_feat[(size_t)NBT * NPIX * FEAT];    // final features [bt][n][128]
__device__ float g_M   [2ULL * Bsz * MTX];             // [which(0=h,1=v)][b][n][m]
__device__ float g_vmax[Bsz * NPIX];
__device__ float g_hmax[Bsz * NPIX];
__device__ float g_vs  [Bsz * NPIX];
__device__ float g_hs  [Bsz * NPIX];

// ---------------- small kernels ----------------
__global__ void k_zero(float* out) { if (threadIdx.x == 0) out[0] = 0.f; }

__global__ void k_theta(const float* __restrict__ noise, const int* __restrict__ swp) {
    int idx = threadIdx.x;
    if (idx >= NBT) return;
    int t = idx >> 2, b = idx & 3;
    const float* nz = noise + (size_t)(t * Bsz + b) * 9;
    double f[9];
    f[0] = 1.0 + 0.05 * (double)nz[0]; f[1] = 0.05 * (double)nz[1]; f[2] = 0.05 * (double)nz[2];
    f[3] = 0.05 * (double)nz[3]; f[4] = 1.0 + 0.05 * (double)nz[4]; f[5] = 0.05 * (double)nz[5];
    f[6] = 0.0; f[7] = 0.0; f[8] = 1.0;
    double det = f[0]*(f[4]*f[8]-f[5]*f[7]) - f[1]*(f[3]*f[8]-f[5]*f[6]) + f[2]*(f[3]*f[7]-f[4]*f[6]);
    double inv[9];
    inv[0] = (f[4]*f[8]-f[5]*f[7])/det; inv[1] = (f[2]*f[7]-f[1]*f[8])/det; inv[2] = (f[1]*f[5]-f[2]*f[4])/det;
    inv[3] = (f[5]*f[6]-f[3]*f[8])/det; inv[4] = (f[0]*f[8]-f[2]*f[6])/det; inv[5] = (f[2]*f[3]-f[0]*f[5])/det;
    inv[6] = (f[3]*f[7]-f[4]*f[6])/det; inv[7] = (f[1]*f[6]-f[0]*f[7])/det; inv[8] = (f[0]*f[4]-f[1]*f[3])/det;
    bool s = (swp[t] == 1);
    for (int k = 0; k < 6; k++) {
        g_thetaA[idx][k] = (float)(s ? inv[k] : f[k]);
        g_thetaB[idx][k] = (float)(s ? f[k]   : inv[k]);
    }
}

// grid coords (torch affine_grid + grid_sample, align_corners=False)
__device__ __forceinline__ void grid_coords(const float* th, int i, int j, float& x, float& y) {
    float sx = (2.f * j + 1.f) * (1.f / Ww) - 1.f;
    float sy = (2.f * i + 1.f) * (1.f / Hh) - 1.f;
    float gx = th[0] * sx + th[1] * sy + th[2];
    float gy = th[3] * sx + th[4] * sy + th[5];
    x = (gx + 1.f) * (Ww * 0.5f) - 0.5f;
    y = (gy + 1.f) * (Hh * 0.5f) - 0.5f;
}

// Sample rolled input through theta_A. 1 thread per (bt, pixel), all 3 channels.
__global__ void k_sample_in(const float* __restrict__ ina, const float* __restrict__ inb,
                            const int* __restrict__ u_roll, const int* __restrict__ v_roll) {
    int idx = blockIdx.x * blockDim.x + threadIdx.x;
    if (idx >= NBT * NPIX) return;
    int bt = idx / NPIX, p = idx - bt * NPIX;
    int t = bt >> 2, b = bt & 3;
    int i = p / Ww, j = p - i * Ww;
    float x, y;
    grid_coords(g_thetaA[bt], i, j, x, y);
    float x0f = floorf(x), y0f = floorf(y);
    float wx1 = x - x0f, wx0 = 1.f - wx1, wy1 = y - y0f, wy0 = 1.f - wy1;
    int ix0 = (int)x0f, iy0 = (int)y0f, ix1 = ix0 + 1, iy1 = iy0 + 1;
    int u = u_roll[t * Bsz + b], v = v_roll[t * Bsz + b];
    const float* X = ((t & 1) ? inb : ina) + (size_t)b * C_IN * NPIX;
    float acc0 = 0.f, acc1 = 0.f, acc2 = 0.f;
    int ixs[4] = {ix0, ix1, ix0, ix1};
    int iys[4] = {iy0, iy0, iy1, iy1};
    float wts[4] = {wx0 * wy0, wx1 * wy0, wx0 * wy1, wx1 * wy1};
#pragma unroll
    for (int c = 0; c < 4; c++) {
        int ix = ixs[c], iy = iys[c];
        if (ix >= 0 && ix < Ww && iy >= 0 && iy < Hh) {
            int rr = (iy + u) % Hh, rc = (ix + v) % Ww;
            int off = rr * Ww + rc;
            float w = wts[c];
            acc0 += w * X[off];
            acc1 += w * X[NPIX + off];
            acc2 += w * X[2 * NPIX + off];
        }
    }
    float* dst = g_xw + (size_t)bt * C_IN * NPIX + p;
    dst[0] = acc0; dst[NPIX] = acc1; dst[2 * NPIX] = acc2;
}

// conv 3x3 SAME (3->64) + ReLU. block = (pixel, bt), 64 threads = out channels.
__global__ void k_conv1(const float* __restrict__ w1, const float* __restrict__ b1) {
    int p = blockIdx.x, bt = blockIdx.y, oc = threadIdx.x;
    int i = p / Ww, j = p - i * Ww;
    const float* xin = g_xw + (size_t)bt * C_IN * NPIX;
    const float* wv = w1 + oc * 27;
    float acc = b1[oc];
#pragma unroll
    for (int ky = 0; ky < 3; ky++) {
        int yy = i + ky - 1;
        if (yy < 0 || yy >= Hh) continue;
#pragma unroll
        for (int kx = 0; kx < 3; kx++) {
            int xx = j + kx - 1;
            if (xx < 0 || xx >= Ww) continue;
            int off = yy * Ww + xx;
#pragma unroll
            for (int ic = 0; ic < 3; ic++)
                acc += __ldg(&xin[ic * NPIX + off]) * wv[ic * 9 + ky * 3 + kx];
        }
    }
    g_h[((size_t)bt * NPIX + p) * HID + oc] = fmaxf(acc, 0.f);
}

// conv 1x1 (64->128). block handles 30 pixels; 128 threads = out channels.
#define PXB 30
__global__ void k_conv2(const float* __restrict__ w2, const float* __restrict__ b2) {
    __shared__ float w2s[HID * FEAT];   // [ic][oc]
    __shared__ float hsm[PXB][HID];
    int bt = blockIdx.y, chunk = blockIdx.x, tid = threadIdx.x;
    for (int ii = tid; ii < HID * FEAT; ii += 128) {
        int ic = ii >> 7, oc = ii & 127;
        w2s[ii] = w2[oc * HID + ic];
    }
    int p0 = chunk * PXB;
    const float* hsrc = g_h + ((size_t)bt * NPIX + p0) * HID;
    for (int ii = tid; ii < PXB * HID; ii += 128) hsm[ii >> 6][ii & 63] = hsrc[ii];
    __syncthreads();
    int oc = tid;
    float bias = b2[oc];
    float* ydst = g_y + ((size_t)bt * NPIX + p0) * FEAT + oc;
    for (int px = 0; px < PXB; px++) {
        float acc = bias;
#pragma unroll
        for (int ic = 0; ic < HID; ic++) acc += hsm[px][ic] * w2s[ic * FEAT + oc];
        ydst[(size_t)px * FEAT] = acc;
    }
}

// grid_sample(y, theta_B) + inverse rolls folded into write index -> g_feat.
__global__ void k_sample_out(const int* __restrict__ u_roll, const int* __restrict__ v_roll) {
    int p = blockIdx.x, bt = blockIdx.y, c = threadIdx.x;
    int t = bt >> 2, b = bt & 3;
    int i = p / Ww, j = p - i * Ww;
    float x, y;
    grid_coords(g_thetaB[bt], i, j, x, y);
    float x0f = floorf(x), y0f = floorf(y);
    float wx1 = x - x0f, wx0 = 1.f - wx1, wy1 = y - y0f, wy0 = 1.f - wy1;
    int ix0 = (int)x0f, iy0 = (int)y0f, ix1 = ix0 + 1, iy1 = iy0 + 1;
    int ixs[4] = {ix0, ix1, ix0, ix1};
    int iys[4] = {iy0, iy0, iy1, iy1};
    float wts[4] = {wx0 * wy0, wx1 * wy0, wx0 * wy1, wx1 * wy1};
    int offs[4]; float ws[4];
#pragma unroll
    for (int k = 0; k < 4; k++) {
        int ix = ixs[k], iy = iys[k];
        bool valid = (ix >= 0 && ix < Ww && iy >= 0 && iy < Hh);
        int col = min(max(ix, 0), Ww - 1), row = min(max(iy, 0), Hh - 1);
        offs[k] = row * Ww + col;
        ws[k] = valid ? wts[k] : 0.f;
    }
    const float* Y = g_y + (size_t)bt * NPIX * FEAT;
    float acc = ws[0] * Y[(size_t)offs[0] * FEAT + c]
              + ws[1] * Y[(size_t)offs[1] * FEAT + c]
              + ws[2] * Y[(size_t)offs[2] * FEAT + c]
              + ws[3] * Y[(size_t)offs[3] * FEAT + c];
    int u = u_roll[t * Bsz + b], v = v_roll[t * Bsz + b];
    int n = ((i + u) % Hh) * Ww + ((j + v) % Ww);
    g_feat[((size_t)bt * NPIX + n) * FEAT + c] = acc;
}

// ---------------- GEMM: M[b][n][m] = dot(featA[b][n], featB[b][m]) ----------------
#define BM 64
#define BN 64
#define BKK 16
__global__ void k_gemm() {
    int bz = blockIdx.z;
    int which = bz >> 2, b = bz & 3;
    const float* A = g_feat + ((size_t)((which * 2 + 0) * Bsz + b)) * NPIX * FEAT;
    const float* Bf = g_feat + ((size_t)((which * 2 + 1) * Bsz + b)) * NPIX * FEAT;
    float* C = g_M + (size_t)(which * Bsz + b) * MTX;
    int n0 = blockIdx.y * BM, m0 = blockIdx.x * BN;
    __shared__ float As[BKK][BM];
    __shared__ float Bs[BKK][BN];
    int tid = threadIdx.x;
    int tx = tid & 15, ty = tid >> 4;
    float acc[4][4] = {};
    int lk = tid & 15, lr0 = tid >> 4;
    for (int k0 = 0; k0 < FEAT; k0 += BKK) {
#pragma unroll
        for (int i = 0; i < 4; i++) {
            int r = lr0 + i * 16;
            int nr = n0 + r, mr = m0 + r;
            As[lk][r] = (nr < NPIX) ? A[(size_t)nr * FEAT + k0 + lk] : 0.f;
            Bs[lk][r] = (mr < NPIX) ? Bf[(size_t)mr * FEAT + k0 + lk] : 0.f;
        }
        __syncthreads();
#pragma unroll
        for (int kk = 0; kk < BKK; kk++) {
            float4 a4 = *(const float4*)&As[kk][ty * 4];
            float4 b4 = *(const float4*)&Bs[kk][tx * 4];
            float a[4] = {a4.x, a4.y, a4.z, a4.w};
            float bb[4] = {b4.x, b4.y, b4.z, b4.w};
#pragma unroll
            for (int i = 0; i < 4; i++)
#pragma unroll
                for (int jx = 0; jx < 4; jx++) acc[i][jx] += a[i] * bb[jx];
        }
        __syncthreads();
    }
#pragma unroll
    for (int i = 0; i < 4; i++) {
        int n = n0 + ty * 4 + i;
        if (n >= NPIX) continue;
#pragma unroll
        for (int jx = 0; jx < 4; jx++) {
            int m = m0 + tx * 4 + jx;
            if (m < NPIX) C[(size_t)n * NPIX + m] = acc[i][jx];
        }
    }
}

// ---------------- reductions ----------------
// column max over Mv: vmax[b][m] = max_n Mv[b][n][m]
__global__ void k_colmax() {
    int idx = blockIdx.x * blockDim.x + threadIdx.x;
    if (idx >= Bsz * NPIX) return;
    int b = idx / NPIX, m = idx - b * NPIX;
    const float* Mv = g_M + (size_t)(Bsz + b) * MTX + m;
    float mx = -1e30f;
#pragma unroll 8
    for (int n = 0; n < NPIX; n++) mx = fmaxf(mx, Mv[(size_t)n * NPIX]);
    g_vmax[idx] = mx;
}

// row max over Mh: hmax[b][n] = max_m Mh[b][n][m] (one warp per row)
__global__ void k_rowmax() {
    int gtid = blockIdx.x * blockDim.x + threadIdx.x;
    int warp = gtid >> 5, lane = gtid & 31;
    if (warp >= Bsz * NPIX) return;
    const float* row = g_M + (size_t)warp * NPIX;  // warp = b*NPIX + n, Mh at offset 0
    float mx = -1e30f;
    for (int m = lane; m < NPIX; m += 32) mx = fmaxf(mx, row[m]);
#pragma unroll
    for (int s = 16; s > 0; s >>= 1) mx = fmaxf(mx, __shfl_xor_sync(0xffffffffu, mx, s));
    if (lane == 0) g_hmax[warp] = mx;
}

__global__ void k_colsum() {
    int idx = blockIdx.x * blockDim.x + threadIdx.x;
    if (idx >= Bsz * NPIX) return;
    int b = idx / NPIX, m = idx - b * NPIX;
    const float* Mv = g_M + (size_t)(Bsz + b) * MTX + m;
    float vmax = g_vmax[idx];
    float s = 0.f;
#pragma unroll 8
    for (int n = 0; n < NPIX; n++) s += __expf(Mv[(size_t)n * NPIX] - vmax);
    g_vs[idx] = 1.f / (s + 1e-4f);
}

__global__ void k_rowsum() {
    int gtid = blockIdx.x * blockDim.x + threadIdx.x;
    int warp = gtid >> 5, lane = gtid & 31;
    if (warp >= Bsz * NPIX) return;
    const float* row = g_M + (size_t)warp * NPIX;
    float hmax = g_hmax[warp];
    float s = 0.f;
    for (int m = lane; m < NPIX; m += 32) s += __expf(row[m] - hmax);
#pragma unroll
    for (int sh = 16; sh > 0; sh >>= 1) s += __shfl_xor_sync(0xffffffffu, s, sh);
    if (lane == 0) g_hs[warp] = 1.f / (s + 1e-4f);
}

// final: out += mean over (b,m) of log(vs[b,m]*sum_n exp(Mv+Mh-vmax-hmax)*hs[b,n] + 1e-4)
__global__ void k_final(float* __restrict__ out) {
    int idx = blockIdx.x * blockDim.x + threadIdx.x;
    float val = 0.f;
    if (idx < Bsz * NPIX) {
        int b = idx / NPIX, m = idx - b * NPIX;
        const float* Mh = g_M + (size_t)b * MTX + m;
        const float* Mv = g_M + (size_t)(Bsz + b) * MTX + m;
        const float* hmax = g_hmax + b * NPIX;
        const float* hsv = g_hs + b * NPIX;
        float vmax = g_vmax[idx];
        float s = 0.f;
#pragma unroll 4
        for (int n = 0; n < NPIX; n++) {
            float e = Mv[(size_t)n * NPIX] - vmax + Mh[(size_t)n * NPIX] - hmax[n];
            s += __expf(e) * hsv[n];
        }
        val = logf(s * g_vs[idx] + 1e-4f) * (1.f / (Bsz * NPIX));
    }
    __shared__ float red[256];
    int tid = threadIdx.x;
    red[tid] = val;
    __syncthreads();
    for (int st = 128; st > 0; st >>= 1) {
        if (tid < st) red[tid] += red[tid + st];
        __syncthreads();
    }
    if (tid == 0) atomicAdd(out, red[0]);
}

// ---------------- launch ----------------
extern "C" void kernel_launch(void* const* d_in, const int* in_sizes, int n_in,
                              void* d_out, int out_size) {
    const float* input_a = (const float*)d_in[0];
    const float* input_b = (const float*)d_in[1];
    const float* w1 = (const float*)d_in[2];
    const float* b1 = (const float*)d_in[3];
    const float* w2 = (const float*)d_in[4];
    const float* b2 = (const float*)d_in[5];
    const float* noise = (const float*)d_in[6];
    const int* u_roll = (const int*)d_in[7];
    const int* v_roll = (const int*)d_in[8];
    const int* swp = (const int*)d_in[9];
    float* out = (float*)d_out;

    k_zero<<<1, 32>>>(out);
    k_theta<<<1, 32>>>(noise, swp);
    k_sample_in<<<(NBT * NPIX + 255) / 256, 256>>>(input_a, input_b, u_roll, v_roll);
    k_conv1<<<dim3(NPIX, NBT), HID>>>(w1, b1);
    k_conv2<<<dim3(NPIX / PXB, NBT), FEAT>>>(w2, b2);
    k_sample_out<<<dim3(NPIX, NBT), FEAT>>>(u_roll, v_roll);
    k_gemm<<<dim3((NPIX + BN - 1) / BN, (NPIX + BM - 1) / BM, 8), 256>>>();
    k_colmax<<<(Bsz * NPIX + 255) / 256, 256>>>();
    k_rowmax<<<(Bsz * NPIX * 32 + 255) / 256, 256>>>();
    k_colsum<<<(Bsz * NPIX + 255) / 256, 256>>>();
    k_rowsum<<<(Bsz * NPIX * 32 + 255) / 256, 256>>>();
    k_final<<<(Bsz * NPIX + 255) / 256, 256>>>(out);
}

// round 2
// speedup vs baseline: 2.6548x; 2.6548x over previous
#include <cuda_runtime.h>
#include <math.h>

// ---------------- problem constants ----------------
#define Bsz   4
#define C_IN  3
#define Hh    60
#define Ww    60
#define NPIX  3600          // H*W
#define HID   64
#define FEAT  128
#define NBT   16            // 4 transforms x 4 batches
#define MTX   12960000ULL   // NPIX*NPIX
#define NSTAT (Bsz * NPIX)  // 14400
#define NCH   240           // rows per reduction chunk (3600/15)

// ---------------- device scratch ----------------
__device__ float g_thetaA[NBT][6];
__device__ float g_thetaB[NBT][6];
__device__ float g_xw  [NBT * C_IN * NPIX];
__device__ float g_h   [(size_t)NBT * NPIX * HID];
__device__ float g_y   [(size_t)NBT * NPIX * FEAT];
__device__ float g_feat[(size_t)NBT * NPIX * FEAT];
__device__ float g_M   [2ULL * Bsz * MTX];          // [which(0=h,1=v)][b][n][m]
__device__ unsigned g_hmax_u[NSTAT];
__device__ unsigned g_vmax_u[NSTAT];
__device__ float g_hs  [NSTAT];
__device__ float g_vsum[NSTAT];
__device__ float g_fsum[NSTAT];

// ordered-uint encoding for float atomicMax
__device__ __forceinline__ unsigned enc(float f) {
    unsigned u = __float_as_uint(f);
    return (u & 0x80000000u) ? ~u : (u | 0x80000000u);
}
__device__ __forceinline__ float dec(unsigned k) {
    return __uint_as_float((k & 0x80000000u) ? (k & 0x7fffffffu) : ~k);
}

// ---------------- init ----------------
__global__ void k_init(float* out) {
    int idx = blockIdx.x * blockDim.x + threadIdx.x;
    if (idx == 0) out[0] = 0.f;
    if (idx < NSTAT) {
        unsigned ninf = enc(-3e38f);
        g_hmax_u[idx] = ninf;
        g_vmax_u[idx] = ninf;
        g_vsum[idx] = 0.f;
        g_fsum[idx] = 0.f;
    }
}

__global__ void k_theta(const float* __restrict__ noise, const int* __restrict__ swp) {
    int idx = threadIdx.x;
    if (idx >= NBT) return;
    int t = idx >> 2, b = idx & 3;
    const float* nz = noise + (size_t)(t * Bsz + b) * 9;
    double f[9];
    f[0] = 1.0 + 0.05 * (double)nz[0]; f[1] = 0.05 * (double)nz[1]; f[2] = 0.05 * (double)nz[2];
    f[3] = 0.05 * (double)nz[3]; f[4] = 1.0 + 0.05 * (double)nz[4]; f[5] = 0.05 * (double)nz[5];
    f[6] = 0.0; f[7] = 0.0; f[8] = 1.0;
    double det = f[0]*(f[4]*f[8]-f[5]*f[7]) - f[1]*(f[3]*f[8]-f[5]*f[6]) + f[2]*(f[3]*f[7]-f[4]*f[6]);
    double inv[9];
    inv[0] = (f[4]*f[8]-f[5]*f[7])/det; inv[1] = (f[2]*f[7]-f[1]*f[8])/det; inv[2] = (f[1]*f[5]-f[2]*f[4])/det;
    inv[3] = (f[5]*f[6]-f[3]*f[8])/det; inv[4] = (f[0]*f[8]-f[2]*f[6])/det; inv[5] = (f[2]*f[3]-f[0]*f[5])/det;
    inv[6] = (f[3]*f[7]-f[4]*f[6])/det; inv[7] = (f[1]*f[6]-f[0]*f[7])/det; inv[8] = (f[0]*f[4]-f[1]*f[3])/det;
    bool s = (swp[t] == 1);
    for (int k = 0; k < 6; k++) {
        g_thetaA[idx][k] = (float)(s ? inv[k] : f[k]);
        g_thetaB[idx][k] = (float)(s ? f[k]   : inv[k]);
    }
}

__device__ __forceinline__ void grid_coords(const float* th, int i, int j, float& x, float& y) {
    float sx = (2.f * j + 1.f) * (1.f / Ww) - 1.f;
    float sy = (2.f * i + 1.f) * (1.f / Hh) - 1.f;
    float gx = th[0] * sx + th[1] * sy + th[2];
    float gy = th[3] * sx + th[4] * sy + th[5];
    x = (gx + 1.f) * (Ww * 0.5f) - 0.5f;
    y = (gy + 1.f) * (Hh * 0.5f) - 0.5f;
}

__global__ void k_sample_in(const float* __restrict__ ina, const float* __restrict__ inb,
                            const int* __restrict__ u_roll, const int* __restrict__ v_roll) {
    int idx = blockIdx.x * blockDim.x + threadIdx.x;
    if (idx >= NBT * NPIX) return;
    int bt = idx / NPIX, p = idx - bt * NPIX;
    int t = bt >> 2, b = bt & 3;
    int i = p / Ww, j = p - i * Ww;
    float x, y;
    grid_coords(g_thetaA[bt], i, j, x, y);
    float x0f = floorf(x), y0f = floorf(y);
    float wx1 = x - x0f, wx0 = 1.f - wx1, wy1 = y - y0f, wy0 = 1.f - wy1;
    int ix0 = (int)x0f, iy0 = (int)y0f, ix1 = ix0 + 1, iy1 = iy0 + 1;
    int u = u_roll[t * Bsz + b], v = v_roll[t * Bsz + b];
    const float* X = ((t & 1) ? inb : ina) + (size_t)b * C_IN * NPIX;
    float acc0 = 0.f, acc1 = 0.f, acc2 = 0.f;
    int ixs[4] = {ix0, ix1, ix0, ix1};
    int iys[4] = {iy0, iy0, iy1, iy1};
    float wts[4] = {wx0 * wy0, wx1 * wy0, wx0 * wy1, wx1 * wy1};
#pragma unroll
    for (int c = 0; c < 4; c++) {
        int ix = ixs[c], iy = iys[c];
        if (ix >= 0 && ix < Ww && iy >= 0 && iy < Hh) {
            int rr = (iy + u) % Hh, rc = (ix + v) % Ww;
            int off = rr * Ww + rc;
            float w = wts[c];
            acc0 += w * X[off];
            acc1 += w * X[NPIX + off];
            acc2 += w * X[2 * NPIX + off];
        }
    }
    float* dst = g_xw + (size_t)bt * C_IN * NPIX + p;
    dst[0] = acc0; dst[NPIX] = acc1; dst[2 * NPIX] = acc2;
}

// conv 3x3 SAME (3->64)+ReLU. block=(row i, bt), 256 thr = 64 oc x 4 pixels
__global__ void k_conv1(const float* __restrict__ w1, const float* __restrict__ b1) {
    __shared__ float xs[3][3][62];   // [ic][ky][col -1..60]
    __shared__ float ws[64 * 27];
    int i = blockIdx.x, bt = blockIdx.y, tid = threadIdx.x;
    int oc = tid & 63, jj = tid >> 6;
    const float* xin = g_xw + (size_t)bt * C_IN * NPIX;
    for (int idx = tid; idx < 3 * 3 * 62; idx += 256) {
        int c = idx / 186, rem = idx - c * 186;
        int rr = rem / 62, cc = rem - rr * 62 - 1;
        int y = i + rr - 1;
        bool valid = (y >= 0 && y < Hh && cc >= 0 && cc < Ww);
        xs[c][rr][rem - rr * 62] = valid ? xin[c * NPIX + y * Ww + cc] : 0.f;
    }
    for (int idx = tid; idx < 64 * 27; idx += 256) ws[idx] = w1[idx];
    __syncthreads();
    float bias = b1[oc];
    const float* wv = ws + oc * 27;
    for (int jq = 0; jq < 15; jq++) {
        int j = jq * 4 + jj;
        float acc = bias;
#pragma unroll
        for (int ic = 0; ic < 3; ic++)
#pragma unroll
            for (int ky = 0; ky < 3; ky++)
#pragma unroll
                for (int kx = 0; kx < 3; kx++)
                    acc += xs[ic][ky][j + kx] * wv[ic * 9 + ky * 3 + kx];
        g_h[((size_t)bt * NPIX + i * Ww + j) * HID + oc] = fmaxf(acc, 0.f);
    }
}

#define PXB 30
__global__ void k_conv2(const float* __restrict__ w2, const float* __restrict__ b2) {
    __shared__ float w2s[HID * FEAT];
    __shared__ float hsm[PXB][HID];
    int bt = blockIdx.y, chunk = blockIdx.x, tid = threadIdx.x;
    for (int ii = tid; ii < HID * FEAT; ii += 128) {
        int ic = ii >> 7, oc = ii & 127;
        w2s[ii] = w2[oc * HID + ic];
    }
    int p0 = chunk * PXB;
    const float* hsrc = g_h + ((size_t)bt * NPIX + p0) * HID;
    for (int ii = tid; ii < PXB * HID; ii += 128) hsm[ii >> 6][ii & 63] = hsrc[ii];
    __syncthreads();
    int oc = tid;
    float bias = b2[oc];
    float* ydst = g_y + ((size_t)bt * NPIX + p0) * FEAT + oc;
    for (int px = 0; px < PXB; px++) {
        float acc = bias;
#pragma unroll
        for (int ic = 0; ic < HID; ic++) acc += hsm[px][ic] * w2s[ic * FEAT + oc];
        ydst[(size_t)px * FEAT] = acc;
    }
}

__global__ void k_sample_out(const int* __restrict__ u_roll, const int* __restrict__ v_roll) {
    int p = blockIdx.x, bt = blockIdx.y, c = threadIdx.x;
    int t = bt >> 2, b = bt & 3;
    int i = p / Ww, j = p - i * Ww;
    float x, y;
    grid_coords(g_thetaB[bt], i, j, x, y);
    float x0f = floorf(x), y0f = floorf(y);
    float wx1 = x - x0f, wx0 = 1.f - wx1, wy1 = y - y0f, wy0 = 1.f - wy1;
    int ix0 = (int)x0f, iy0 = (int)y0f, ix1 = ix0 + 1, iy1 = iy0 + 1;
    int ixs[4] = {ix0, ix1, ix0, ix1};
    int iys[4] = {iy0, iy0, iy1, iy1};
    float wts[4] = {wx0 * wy0, wx1 * wy0, wx0 * wy1, wx1 * wy1};
    int offs[4]; float wsv[4];
#pragma unroll
    for (int k = 0; k < 4; k++) {
        int ix = ixs[k], iy = iys[k];
        bool valid = (ix >= 0 && ix < Ww && iy >= 0 && iy < Hh);
        int col = min(max(ix, 0), Ww - 1), row = min(max(iy, 0), Hh - 1);
        offs[k] = row * Ww + col;
        wsv[k] = valid ? wts[k] : 0.f;
    }
    const float* Y = g_y + (size_t)bt * NPIX * FEAT;
    float acc = wsv[0] * Y[(size_t)offs[0] * FEAT + c]
              + wsv[1] * Y[(size_t)offs[1] * FEAT + c]
              + wsv[2] * Y[(size_t)offs[2] * FEAT + c]
              + wsv[3] * Y[(size_t)offs[3] * FEAT + c];
    int u = u_roll[t * Bsz + b], v = v_roll[t * Bsz + b];
    int n = ((i + u) % Hh) * Ww + ((j + v) % Ww);
    g_feat[((size_t)bt * NPIX + n) * FEAT + c] = acc;
}

// ---------------- GEMM 128x128 tile, 8x8/thread, double-buffered ----------------
// which==0 (Mh): epilogue also computes row-max partials -> g_hmax_u
// which==1 (Mv): epilogue also computes col-max partials -> g_vmax_u
#define TB 128
__global__ void __launch_bounds__(256) k_gemm() {
    int bz = blockIdx.z;
    int which = bz >> 2, b = bz & 3;
    const float* A  = g_feat + (size_t)((which * 2 + 0) * Bsz + b) * NPIX * FEAT;
    const float* Bf = g_feat + (size_t)((which * 2 + 1) * Bsz + b) * NPIX * FEAT;
    float* C = g_M + (size_t)(which * Bsz + b) * MTX;
    int n0 = blockIdx.y * TB, m0 = blockIdx.x * TB;

    __shared__ float As[2][8][132];
    __shared__ float Bs[2][8][132];
    __shared__ float red[16][128];

    int tid = threadIdx.x;
    int lr = tid >> 1, lq = (tid & 1) << 2;    // loader: row 0..127, k offset {0,4}
    int tx = tid & 15, ty = tid >> 4;          // compute: 16x16 threads

    float4 pa, pb;
    {
        int ar = n0 + lr, br = m0 + lr;
        pa = (ar < NPIX) ? *(const float4*)(A  + (size_t)ar * FEAT + lq) : make_float4(0, 0, 0, 0);
        pb = (br < NPIX) ? *(const float4*)(Bf + (size_t)br * FEAT + lq) : make_float4(0, 0, 0, 0);
    }
    As[0][lq + 0][lr] = pa.x; As[0][lq + 1][lr] = pa.y; As[0][lq + 2][lr] = pa.z; As[0][lq + 3][lr] = pa.w;
    Bs[0][lq + 0][lr] = pb.x; Bs[0][lq + 1][lr] = pb.y; Bs[0][lq + 2][lr] = pb.z; Bs[0][lq + 3][lr] = pb.w;
    __syncthreads();

    float acc[8][8] = {};
    for (int kt = 0; kt < 16; kt++) {
        int cur = kt & 1;
        if (kt < 15) {
            int k = (kt + 1) * 8 + lq;
            int ar = n0 + lr, br = m0 + lr;
            pa = (ar < NPIX) ? *(const float4*)(A  + (size_t)ar * FEAT + k) : make_float4(0, 0, 0, 0);
            pb = (br < NPIX) ? *(const float4*)(Bf + (size_t)br * FEAT + k) : make_float4(0, 0, 0, 0);
        }
#pragma unroll
        for (int kk = 0; kk < 8; kk++) {
            float a[8], bb[8];
            *(float4*)(a)      = *(const float4*)&As[cur][kk][ty * 8];
            *(float4*)(a + 4)  = *(const float4*)&As[cur][kk][ty * 8 + 4];
            *(float4*)(bb)     = *(const float4*)&Bs[cur][kk][tx * 8];
            *(float4*)(bb + 4) = *(const float4*)&Bs[cur][kk][tx * 8 + 4];
#pragma unroll
            for (int i = 0; i < 8; i++)
#pragma unroll
                for (int jx = 0; jx < 8; jx++) acc[i][jx] += a[i] * bb[jx];
        }
        if (kt < 15) {
            int nb = cur ^ 1;
            As[nb][lq + 0][lr] = pa.x; As[nb][lq + 1][lr] = pa.y; As[nb][lq + 2][lr] = pa.z; As[nb][lq + 3][lr] = pa.w;
            Bs[nb][lq + 0][lr] = pb.x; Bs[nb][lq + 1][lr] = pb.y; Bs[nb][lq + 2][lr] = pb.z; Bs[nb][lq + 3][lr] = pb.w;
        }
        __syncthreads();
    }

    // store C (3600 % 8 == 0 -> per-thread all-or-nothing column validity)
    bool cvalid = (m0 + tx * 8) < NPIX;
#pragma unroll
    for (int i = 0; i < 8; i++) {
        int n = n0 + ty * 8 + i;
        if (n < NPIX && cvalid) {
            float* crow = C + (size_t)n * NPIX + m0 + tx * 8;
            *(float4*)(crow)     = make_float4(acc[i][0], acc[i][1], acc[i][2], acc[i][3]);
            *(float4*)(crow + 4) = make_float4(acc[i][4], acc[i][5], acc[i][6], acc[i][7]);
        }
    }

    // fused max reduction
    bool rvalid = (n0 + ty * 8) < NPIX;
    if (which == 0) {
        // row max over valid columns
#pragma unroll
        for (int i = 0; i < 8; i++) {
            float r = -3e38f;
            if (cvalid) {
#pragma unroll
                for (int jx = 0; jx < 8; jx++) r = fmaxf(r, acc[i][jx]);
            }
            red[tx][ty * 8 + i] = r;
        }
        __syncthreads();
        if (tid < 128) {
            float r = red[0][tid];
#pragma unroll
            for (int t = 1; t < 16; t++) r = fmaxf(r, red[t][tid]);
            int n = n0 + tid;
            if (n < NPIX) atomicMax(&g_hmax_u[b * NPIX + n], enc(r));
        }
    } else {
        // col max over valid rows
#pragma unroll
        for (int jx = 0; jx < 8; jx++) {
            float r = -3e38f;
            if (rvalid) {
#pragma unroll
                for (int i = 0; i < 8; i++) r = fmaxf(r, acc[i][jx]);
            }
            red[ty][tx * 8 + jx] = r;
        }
        __syncthreads();
        if (tid < 128) {
            float r = red[0][tid];
#pragma unroll
            for (int t = 1; t < 16; t++) r = fmaxf(r, red[t][tid]);
            int m = m0 + tid;
            if (m < NPIX) atomicMax(&g_vmax_u[b * NPIX + m], enc(r));
        }
    }
}

// row sums of Mh -> hs (one warp per row)
__global__ void k_rowsum() {
    int gtid = blockIdx.x * blockDim.x + threadIdx.x;
    int warp = gtid >> 5, lane = gtid & 31;
    if (warp >= NSTAT) return;
    const float* row = g_M + (size_t)warp * NPIX;
    float hmax = dec(g_hmax_u[warp]);
    float s = 0.f;
    for (int m = lane; m < NPIX; m += 32) s += __expf(row[m] - hmax);
#pragma unroll
    for (int sh = 16; sh > 0; sh >>= 1) s += __shfl_xor_sync(0xffffffffu, s, sh);
    if (lane == 0) g_hs[warp] = 1.f / (s + 1e-4f);
}

// col sums of Mv -> g_vsum (grid-split over n with atomicAdd)
__global__ void k_colsum() {
    int m = blockIdx.x * 256 + threadIdx.x;
    if (m >= NPIX) return;
    int b = blockIdx.z, n0 = blockIdx.y * NCH;
    float vmax = dec(g_vmax_u[b * NPIX + m]);
    const float* Mv = g_M + (size_t)(Bsz + b) * MTX + (size_t)n0 * NPIX + m;
    float s = 0.f;
#pragma unroll 8
    for (int n = 0; n < NCH; n++) s += __expf(Mv[(size_t)n * NPIX] - vmax);
    atomicAdd(&g_vsum[b * NPIX + m], s);
}

// final joint pass -> g_fsum (grid-split over n with atomicAdd)
__global__ void k_final() {
    __shared__ float sh_hm[NCH], sh_hs[NCH];
    int tid = threadIdx.x;
    int b = blockIdx.z, n0 = blockIdx.y * NCH;
    if (tid < NCH) {
        sh_hm[tid] = dec(g_hmax_u[b * NPIX + n0 + tid]);
        sh_hs[tid] = g_hs[b * NPIX + n0 + tid];
    }
    __syncthreads();
    int m = blockIdx.x * 256 + tid;
    if (m >= NPIX) return;
    float vmax = dec(g_vmax_u[b * NPIX + m]);
    const float* Mh = g_M + (size_t)b * MTX + (size_t)n0 * NPIX + m;
    const float* Mv = g_M + (size_t)(Bsz + b) * MTX + (size_t)n0 * NPIX + m;
    float s = 0.f;
#pragma unroll 4
    for (int n = 0; n < NCH; n++) {
        float e = Mv[(size_t)n * NPIX] - vmax + Mh[(size_t)n * NPIX] - sh_hm[n];
        s += __expf(e) * sh_hs[n];
    }
    atomicAdd(&g_fsum[b * NPIX + m], s);
}

__global__ void k_logmean(float* __restrict__ out) {
    int idx = blockIdx.x * blockDim.x + threadIdx.x;
    float val = 0.f;
    if (idx < NSTAT)
        val = logf(g_fsum[idx] / (g_vsum[idx] + 1e-4f) + 1e-4f) * (1.f / NSTAT);
    __shared__ float red[256];
    int tid = threadIdx.x;
    red[tid] = val;
    __syncthreads();
    for (int st = 128; st > 0; st >>= 1) {
        if (tid < st) red[tid] += red[tid + st];
        __syncthreads();
    }
    if (tid == 0) atomicAdd(out, red[0]);
}

// ---------------- launch ----------------
extern "C" void kernel_launch(void* const* d_in, const int* in_sizes, int n_in,
                              void* d_out, int out_size) {
    const float* input_a = (const float*)d_in[0];
    const float* input_b = (const float*)d_in[1];
    const float* w1 = (const float*)d_in[2];
    const float* b1 = (const float*)d_in[3];
    const float* w2 = (const float*)d_in[4];
    const float* b2 = (const float*)d_in[5];
    const float* noise = (const float*)d_in[6];
    const int* u_roll = (const int*)d_in[7];
    const int* v_roll = (const int*)d_in[8];
    const int* swp = (const int*)d_in[9];
    float* out = (float*)d_out;

    k_init<<<(NSTAT + 255) / 256, 256>>>(out);
    k_theta<<<1, 32>>>(noise, swp);
    k_sample_in<<<(NBT * NPIX + 255) / 256, 256>>>(input_a, input_b, u_roll, v_roll);
    k_conv1<<<dim3(Hh, NBT), 256>>>(w1, b1);
    k_conv2<<<dim3(NPIX / PXB, NBT), FEAT>>>(w2, b2);
    k_sample_out<<<dim3(NPIX, NBT), FEAT>>>(u_roll, v_roll);
    int nt = (NPIX + TB - 1) / TB;  // 29
    k_gemm<<<dim3(nt, nt, 8), 256>>>();
    k_rowsum<<<(NSTAT * 32 + 255) / 256, 256>>>();
    k_colsum<<<dim3(15, NPIX / NCH, Bsz), 256>>>();
    k_final<<<dim3(15, NPIX / NCH, Bsz), 256>>>();
    k_logmean<<<(NSTAT + 255) / 256, 256>>>(out);
}

// round 3
// speedup vs baseline: 2.6624x; 1.0029x over previous
#include <cuda_runtime.h>
#include <math.h>

// ---------------- problem constants ----------------
#define Bsz   4
#define C_IN  3
#define Hh    60
#define Ww    60
#define NPIX  3600          // H*W
#define HID   64
#define FEAT  128
#define NBT   16            // 4 transforms x 4 batches
#define MTX   12960000ULL   // NPIX*NPIX
#define NSTAT (Bsz * NPIX)  // 14400
#define NCH   240           // rows per reduction chunk (3600/15)

// ---------------- device scratch ----------------
__device__ float g_thetaA[NBT][6];
__device__ float g_thetaB[NBT][6];
__device__ float g_xw  [NBT * C_IN * NPIX];
__device__ float g_h   [(size_t)NBT * NPIX * HID];
__device__ float g_y   [(size_t)NBT * NPIX * FEAT];
__device__ float g_feat[(size_t)NBT * NPIX * FEAT];
__device__ float g_M   [2ULL * Bsz * MTX];          // [which(0=h,1=v)][b][n][m]
__device__ unsigned g_hmax_u[NSTAT];
__device__ unsigned g_vmax_u[NSTAT];
__device__ float g_hs  [NSTAT];
__device__ float g_vsum[NSTAT];
__device__ float g_fsum[NSTAT];

// ordered-uint encoding for float atomicMax
__device__ __forceinline__ unsigned enc(float f) {
    unsigned u = __float_as_uint(f);
    return (u & 0x80000000u) ? ~u : (u | 0x80000000u);
}
__device__ __forceinline__ float dec(unsigned k) {
    return __uint_as_float((k & 0x80000000u) ? (k & 0x7fffffffu) : ~k);
}

// ---------------- init ----------------
__global__ void k_init(float* out) {
    int idx = blockIdx.x * blockDim.x + threadIdx.x;
    if (idx == 0) out[0] = 0.f;
    if (idx < NSTAT) {
        unsigned ninf = enc(-3e38f);
        g_hmax_u[idx] = ninf;
        g_vmax_u[idx] = ninf;
        g_vsum[idx] = 0.f;
        g_fsum[idx] = 0.f;
    }
}

__global__ void k_theta(const float* __restrict__ noise, const int* __restrict__ swp) {
    int idx = threadIdx.x;
    if (idx >= NBT) return;
    int t = idx >> 2, b = idx & 3;
    const float* nz = noise + (size_t)(t * Bsz + b) * 9;
    double f[9];
    f[0] = 1.0 + 0.05 * (double)nz[0]; f[1] = 0.05 * (double)nz[1]; f[2] = 0.05 * (double)nz[2];
    f[3] = 0.05 * (double)nz[3]; f[4] = 1.0 + 0.05 * (double)nz[4]; f[5] = 0.05 * (double)nz[5];
    f[6] = 0.0; f[7] = 0.0; f[8] = 1.0;
    double det = f[0]*(f[4]*f[8]-f[5]*f[7]) - f[1]*(f[3]*f[8]-f[5]*f[6]) + f[2]*(f[3]*f[7]-f[4]*f[6]);
    double inv[9];
    inv[0] = (f[4]*f[8]-f[5]*f[7])/det; inv[1] = (f[2]*f[7]-f[1]*f[8])/det; inv[2] = (f[1]*f[5]-f[2]*f[4])/det;
    inv[3] = (f[5]*f[6]-f[3]*f[8])/det; inv[4] = (f[0]*f[8]-f[2]*f[6])/det; inv[5] = (f[2]*f[3]-f[0]*f[5])/det;
    inv[6] = (f[3]*f[7]-f[4]*f[6])/det; inv[7] = (f[1]*f[6]-f[0]*f[7])/det; inv[8] = (f[0]*f[4]-f[1]*f[3])/det;
    bool s = (swp[t] == 1);
    for (int k = 0; k < 6; k++) {
        g_thetaA[idx][k] = (float)(s ? inv[k] : f[k]);
        g_thetaB[idx][k] = (float)(s ? f[k]   : inv[k]);
    }
}

__device__ __forceinline__ void grid_coords(const float* th, int i, int j, float& x, float& y) {
    float sx = (2.f * j + 1.f) * (1.f / Ww) - 1.f;
    float sy = (2.f * i + 1.f) * (1.f / Hh) - 1.f;
    float gx = th[0] * sx + th[1] * sy + th[2];
    float gy = th[3] * sx + th[4] * sy + th[5];
    x = (gx + 1.f) * (Ww * 0.5f) - 0.5f;
    y = (gy + 1.f) * (Hh * 0.5f) - 0.5f;
}

__global__ void k_sample_in(const float* __restrict__ ina, const float* __restrict__ inb,
                            const int* __restrict__ u_roll, const int* __restrict__ v_roll) {
    int idx = blockIdx.x * blockDim.x + threadIdx.x;
    if (idx >= NBT * NPIX) return;
    int bt = idx / NPIX, p = idx - bt * NPIX;
    int t = bt >> 2, b = bt & 3;
    int i = p / Ww, j = p - i * Ww;
    float x, y;
    grid_coords(g_thetaA[bt], i, j, x, y);
    float x0f = floorf(x), y0f = floorf(y);
    float wx1 = x - x0f, wx0 = 1.f - wx1, wy1 = y - y0f, wy0 = 1.f - wy1;
    int ix0 = (int)x0f, iy0 = (int)y0f, ix1 = ix0 + 1, iy1 = iy0 + 1;
    int u = u_roll[t * Bsz + b], v = v_roll[t * Bsz + b];
    const float* X = ((t & 1) ? inb : ina) + (size_t)b * C_IN * NPIX;
    float acc0 = 0.f, acc1 = 0.f, acc2 = 0.f;
    int ixs[4] = {ix0, ix1, ix0, ix1};
    int iys[4] = {iy0, iy0, iy1, iy1};
    float wts[4] = {wx0 * wy0, wx1 * wy0, wx0 * wy1, wx1 * wy1};
#pragma unroll
    for (int c = 0; c < 4; c++) {
        int ix = ixs[c], iy = iys[c];
        if (ix >= 0 && ix < Ww && iy >= 0 && iy < Hh) {
            int rr = (iy + u) % Hh, rc = (ix + v) % Ww;
            int off = rr * Ww + rc;
            float w = wts[c];
            acc0 += w * X[off];
            acc1 += w * X[NPIX + off];
            acc2 += w * X[2 * NPIX + off];
        }
    }
    float* dst = g_xw + (size_t)bt * C_IN * NPIX + p;
    dst[0] = acc0; dst[NPIX] = acc1; dst[2 * NPIX] = acc2;
}

// conv 3x3 SAME (3->64)+ReLU. block=(row i, bt), 256 thr = 64 oc x 4 pixels
__global__ void k_conv1(const float* __restrict__ w1, const float* __restrict__ b1) {
    __shared__ float xs[3][3][62];   // [ic][ky][col -1..60]
    __shared__ float ws[64 * 27];
    int i = blockIdx.x, bt = blockIdx.y, tid = threadIdx.x;
    int oc = tid & 63, jj = tid >> 6;
    const float* xin = g_xw + (size_t)bt * C_IN * NPIX;
    for (int idx = tid; idx < 3 * 3 * 62; idx += 256) {
        int c = idx / 186, rem = idx - c * 186;
        int rr = rem / 62, cc = rem - rr * 62 - 1;
        int y = i + rr - 1;
        bool valid = (y >= 0 && y < Hh && cc >= 0 && cc < Ww);
        xs[c][rr][rem - rr * 62] = valid ? xin[c * NPIX + y * Ww + cc] : 0.f;
    }
    for (int idx = tid; idx < 64 * 27; idx += 256) ws[idx] = w1[idx];
    __syncthreads();
    float bias = b1[oc];
    const float* wv = ws + oc * 27;
    for (int jq = 0; jq < 15; jq++) {
        int j = jq * 4 + jj;
        float acc = bias;
#pragma unroll
        for (int ic = 0; ic < 3; ic++)
#pragma unroll
            for (int ky = 0; ky < 3; ky++)
#pragma unroll
                for (int kx = 0; kx < 3; kx++)
                    acc += xs[ic][ky][j + kx] * wv[ic * 9 + ky * 3 + kx];
        g_h[((size_t)bt * NPIX + i * Ww + j) * HID + oc] = fmaxf(acc, 0.f);
    }
}

#define PXB 30
__global__ void k_conv2(const float* __restrict__ w2, const float* __restrict__ b2) {
    __shared__ float w2s[HID * FEAT];
    __shared__ float hsm[PXB][HID];
    int bt = blockIdx.y, chunk = blockIdx.x, tid = threadIdx.x;
    for (int ii = tid; ii < HID * FEAT; ii += 128) {
        int ic = ii >> 7, oc = ii & 127;
        w2s[ii] = w2[oc * HID + ic];
    }
    int p0 = chunk * PXB;
    const float* hsrc = g_h + ((size_t)bt * NPIX + p0) * HID;
    for (int ii = tid; ii < PXB * HID; ii += 128) hsm[ii >> 6][ii & 63] = hsrc[ii];
    __syncthreads();
    int oc = tid;
    float bias = b2[oc];
    float* ydst = g_y + ((size_t)bt * NPIX + p0) * FEAT + oc;
    for (int px = 0; px < PXB; px++) {
        float acc = bias;
#pragma unroll
        for (int ic = 0; ic < HID; ic++) acc += hsm[px][ic] * w2s[ic * FEAT + oc];
        ydst[(size_t)px * FEAT] = acc;
    }
}

__global__ void k_sample_out(const int* __restrict__ u_roll, const int* __restrict__ v_roll) {
    int p = blockIdx.x, bt = blockIdx.y, c = threadIdx.x;
    int t = bt >> 2, b = bt & 3;
    int i = p / Ww, j = p - i * Ww;
    float x, y;
    grid_coords(g_thetaB[bt], i, j, x, y);
    float x0f = floorf(x), y0f = floorf(y);
    float wx1 = x - x0f, wx0 = 1.f - wx1, wy1 = y - y0f, wy0 = 1.f - wy1;
    int ix0 = (int)x0f, iy0 = (int)y0f, ix1 = ix0 + 1, iy1 = iy0 + 1;
    int ixs[4] = {ix0, ix1, ix0, ix1};
    int iys[4] = {iy0, iy0, iy1, iy1};
    float wts[4] = {wx0 * wy0, wx1 * wy0, wx0 * wy1, wx1 * wy1};
    int offs[4]; float wsv[4];
#pragma unroll
    for (int k = 0; k < 4; k++) {
        int ix = ixs[k], iy = iys[k];
        bool valid = (ix >= 0 && ix < Ww && iy >= 0 && iy < Hh);
        int col = min(max(ix, 0), Ww - 1), row = min(max(iy, 0), Hh - 1);
        offs[k] = row * Ww + col;
        wsv[k] = valid ? wts[k] : 0.f;
    }
    const float* Y = g_y + (size_t)bt * NPIX * FEAT;
    float acc = wsv[0] * Y[(size_t)offs[0] * FEAT + c]
              + wsv[1] * Y[(size_t)offs[1] * FEAT + c]
              + wsv[2] * Y[(size_t)offs[2] * FEAT + c]
              + wsv[3] * Y[(size_t)offs[3] * FEAT + c];
    int u = u_roll[t * Bsz + b], v = v_roll[t * Bsz + b];
    int n = ((i + u) % Hh) * Ww + ((j + v) % Ww);
    g_feat[((size_t)bt * NPIX + n) * FEAT + c] = acc;
}

// ---------------- GEMM 128x128 tile, 8x8/thread, double-buffered ----------------
// which==0 (Mh): epilogue also computes row-max partials -> g_hmax_u
// which==1 (Mv): epilogue also computes col-max partials -> g_vmax_u
#define TB 128
__global__ void __launch_bounds__(256) k_gemm() {
    int bz = blockIdx.z;
    int which = bz >> 2, b = bz & 3;
    const float* A  = g_feat + (size_t)((which * 2 + 0) * Bsz + b) * NPIX * FEAT;
    const float* Bf = g_feat + (size_t)((which * 2 + 1) * Bsz + b) * NPIX * FEAT;
    float* C = g_M + (size_t)(which * Bsz + b) * MTX;
    int n0 = blockIdx.y * TB, m0 = blockIdx.x * TB;

    __shared__ float As[2][8][132];
    __shared__ float Bs[2][8][132];
    __shared__ float red[16][128];

    int tid = threadIdx.x;
    int lr = tid >> 1, lq = (tid & 1) << 2;    // loader: row 0..127, k offset {0,4}
    int tx = tid & 15, ty = tid >> 4;          // compute: 16x16 threads

    float4 pa, pb;
    {
        int ar = n0 + lr, br = m0 + lr;
        pa = (ar < NPIX) ? *(const float4*)(A  + (size_t)ar * FEAT + lq) : make_float4(0, 0, 0, 0);
        pb = (br < NPIX) ? *(const float4*)(Bf + (size_t)br * FEAT + lq) : make_float4(0, 0, 0, 0);
    }
    As[0][lq + 0][lr] = pa.x; As[0][lq + 1][lr] = pa.y; As[0][lq + 2][lr] = pa.z; As[0][lq + 3][lr] = pa.w;
    Bs[0][lq + 0][lr] = pb.x; Bs[0][lq + 1][lr] = pb.y; Bs[0][lq + 2][lr] = pb.z; Bs[0][lq + 3][lr] = pb.w;
    __syncthreads();

    float acc[8][8] = {};
    for (int kt = 0; kt < 16; kt++) {
        int cur = kt & 1;
        if (kt < 15) {
            int k = (kt + 1) * 8 + lq;
            int ar = n0 + lr, br = m0 + lr;
            pa = (ar < NPIX) ? *(const float4*)(A  + (size_t)ar * FEAT + k) : make_float4(0, 0, 0, 0);
            pb = (br < NPIX) ? *(const float4*)(Bf + (size_t)br * FEAT + k) : make_float4(0, 0, 0, 0);
        }
#pragma unroll
        for (int kk = 0; kk < 8; kk++) {
            float a[8], bb[8];
            *(float4*)(a)      = *(const float4*)&As[cur][kk][ty * 8];
            *(float4*)(a + 4)  = *(const float4*)&As[cur][kk][ty * 8 + 4];
            *(float4*)(bb)     = *(const float4*)&Bs[cur][kk][tx * 8];
            *(float4*)(bb + 4) = *(const float4*)&Bs[cur][kk][tx * 8 + 4];
#pragma unroll
            for (int i = 0; i < 8; i++)
#pragma unroll
                for (int jx = 0; jx < 8; jx++) acc[i][jx] += a[i] * bb[jx];
        }
        if (kt < 15) {
            int nb = cur ^ 1;
            As[nb][lq + 0][lr] = pa.x; As[nb][lq + 1][lr] = pa.y; As[nb][lq + 2][lr] = pa.z; As[nb][lq + 3][lr] = pa.w;
            Bs[nb][lq + 0][lr] = pb.x; Bs[nb][lq + 1][lr] = pb.y; Bs[nb][lq + 2][lr] = pb.z; Bs[nb][lq + 3][lr] = pb.w;
        }
        __syncthreads();
    }

    // store C (3600 % 8 == 0 -> per-thread all-or-nothing column validity)
    bool cvalid = (m0 + tx * 8) < NPIX;
#pragma unroll
    for (int i = 0; i < 8; i++) {
        int n = n0 + ty * 8 + i;
        if (n < NPIX && cvalid) {
            float* crow = C + (size_t)n * NPIX + m0 + tx * 8;
            *(float4*)(crow)     = make_float4(acc[i][0], acc[i][1], acc[i][2], acc[i][3]);
            *(float4*)(crow + 4) = make_float4(acc[i][4], acc[i][5], acc[i][6], acc[i][7]);
        }
    }

    // fused max reduction
    bool rvalid = (n0 + ty * 8) < NPIX;
    if (which == 0) {
        // row max over valid columns
#pragma unroll
        for (int i = 0; i < 8; i++) {
            float r = -3e38f;
            if (cvalid) {
#pragma unroll
                for (int jx = 0; jx < 8; jx++) r = fmaxf(r, acc[i][jx]);
            }
            red[tx][ty * 8 + i] = r;
        }
        __syncthreads();
        if (tid < 128) {
            float r = red[0][tid];
#pragma unroll
            for (int t = 1; t < 16; t++) r = fmaxf(r, red[t][tid]);
            int n = n0 + tid;
            if (n < NPIX) atomicMax(&g_hmax_u[b * NPIX + n], enc(r));
        }
    } else {
        // col max over valid rows
#pragma unroll
        for (int jx = 0; jx < 8; jx++) {
            float r = -3e38f;
            if (rvalid) {
#pragma unroll
                for (int i = 0; i < 8; i++) r = fmaxf(r, acc[i][jx]);
            }
            red[ty][tx * 8 + jx] = r;
        }
        __syncthreads();
        if (tid < 128) {
            float r = red[0][tid];
#pragma unroll
            for (int t = 1; t < 16; t++) r = fmaxf(r, red[t][tid]);
            int m = m0 + tid;
            if (m < NPIX) atomicMax(&g_vmax_u[b * NPIX + m], enc(r));
        }
    }
}

// row sums of Mh -> hs (one warp per row)
__global__ void k_rowsum() {
    int gtid = blockIdx.x * blockDim.x + threadIdx.x;
    int warp = gtid >> 5, lane = gtid & 31;
    if (warp >= NSTAT) return;
    const float* row = g_M + (size_t)warp * NPIX;
    float hmax = dec(g_hmax_u[warp]);
    float s = 0.f;
    for (int m = lane; m < NPIX; m += 32) s += __expf(row[m] - hmax);
#pragma unroll
    for (int sh = 16; sh > 0; sh >>= 1) s += __shfl_xor_sync(0xffffffffu, s, sh);
    if (lane == 0) g_hs[warp] = 1.f / (s + 1e-4f);
}

// col sums of Mv -> g_vsum (grid-split over n with atomicAdd)
__global__ void k_colsum() {
    int m = blockIdx.x * 256 + threadIdx.x;
    if (m >= NPIX) return;
    int b = blockIdx.z, n0 = blockIdx.y * NCH;
    float vmax = dec(g_vmax_u[b * NPIX + m]);
    const float* Mv = g_M + (size_t)(Bsz + b) * MTX + (size_t)n0 * NPIX + m;
    float s = 0.f;
#pragma unroll 8
    for (int n = 0; n < NCH; n++) s += __expf(Mv[(size_t)n * NPIX] - vmax);
    atomicAdd(&g_vsum[b * NPIX + m], s);
}

// final joint pass -> g_fsum (grid-split over n with atomicAdd)
__global__ void k_final() {
    __shared__ float sh_hm[NCH], sh_hs[NCH];
    int tid = threadIdx.x;
    int b = blockIdx.z, n0 = blockIdx.y * NCH;
    if (tid < NCH) {
        sh_hm[tid] = dec(g_hmax_u[b * NPIX + n0 + tid]);
        sh_hs[tid] = g_hs[b * NPIX + n0 + tid];
    }
    __syncthreads();
    int m = blockIdx.x * 256 + tid;
    if (m >= NPIX) return;
    float vmax = dec(g_vmax_u[b * NPIX + m]);
    const float* Mh = g_M + (size_t)b * MTX + (size_t)n0 * NPIX + m;
    const float* Mv = g_M + (size_t)(Bsz + b) * MTX + (size_t)n0 * NPIX + m;
    float s = 0.f;
#pragma unroll 4
    for (int n = 0; n < NCH; n++) {
        float e = Mv[(size_t)n * NPIX] - vmax + Mh[(size_t)n * NPIX] - sh_hm[n];
        s += __expf(e) * sh_hs[n];
    }
    atomicAdd(&g_fsum[b * NPIX + m], s);
}

__global__ void k_logmean(float* __restrict__ out) {
    int idx = blockIdx.x * blockDim.x + threadIdx.x;
    float val = 0.f;
    if (idx < NSTAT)
        val = logf(g_fsum[idx] / (g_vsum[idx] + 1e-4f) + 1e-4f) * (1.f / NSTAT);
    __shared__ float red[256];
    int tid = threadIdx.x;
    red[tid] = val;
    __syncthreads();
    for (int st = 128; st > 0; st >>= 1) {
        if (tid < st) red[tid] += red[tid + st];
        __syncthreads();
    }
    if (tid == 0) atomicAdd(out, red[0]);
}

// ---------------- launch ----------------
extern "C" void kernel_launch(void* const* d_in, const int* in_sizes, int n_in,
                              void* d_out, int out_size) {
    const float* input_a = (const float*)d_in[0];
    const float* input_b = (const float*)d_in[1];
    const float* w1 = (const float*)d_in[2];
    const float* b1 = (const float*)d_in[3];
    const float* w2 = (const float*)d_in[4];
    const float* b2 = (const float*)d_in[5];
    const float* noise = (const float*)d_in[6];
    const int* u_roll = (const int*)d_in[7];
    const int* v_roll = (const int*)d_in[8];
    const int* swp = (const int*)d_in[9];
    float* out = (float*)d_out;

    k_init<<<(NSTAT + 255) / 256, 256>>>(out);
    k_theta<<<1, 32>>>(noise, swp);
    k_sample_in<<<(NBT * NPIX + 255) / 256, 256>>>(input_a, input_b, u_roll, v_roll);
    k_conv1<<<dim3(Hh, NBT), 256>>>(w1, b1);
    k_conv2<<<dim3(NPIX / PXB, NBT), FEAT>>>(w2, b2);
    k_sample_out<<<dim3(NPIX, NBT), FEAT>>>(u_roll, v_roll);
    int nt = (NPIX + TB - 1) / TB;  // 29
    k_gemm<<<dim3(nt, nt, 8), 256>>>();
    k_rowsum<<<(NSTAT * 32 + 255) / 256, 256>>>();
    k_colsum<<<dim3(15, NPIX / NCH, Bsz), 256>>>();
    k_final<<<dim3(15, NPIX / NCH, Bsz), 256>>>();
    k_logmean<<<(NSTAT + 255) / 256, 256>>>(out);
}